// round 5
// baseline (speedup 1.0000x reference)
#include <cuda_runtime.h>
#include <cstdint>

typedef unsigned long long u64;

// ---------------- constants ----------------
constexpr int THREADS = 512;
constexpr int WARPS   = THREADS / 32;

// smem layout (floats)
constexpr int SM_BES   = 0;                    // 8 x 64 bessel rows of W0
constexpr int SM_W1    = 512;                  // 64 x 128 (prescaled S1)
constexpr int SM_WC    = SM_W1 + 64 * 128;     // 64 x 160 (W1s @ WeS2)
constexpr int SM_CST   = SM_WC + 64 * 160;     // bessel_w[8], tpw[7]
constexpr int SM_STASH = SM_CST + 16;          // WARPS * 1056
constexpr int SM_BUF   = SM_STASH + WARPS * 1056;
constexpr int SMEM_FLOATS = SM_BUF + WARPS * 1056;
constexpr int SMEM_BYTES  = SMEM_FLOATS * 4;   // 211,008 B

// ---------------- device scratch ----------------
__device__ float g_wcombo[64 * 160];

// ---------------- f32x2 helpers ----------------
__device__ __forceinline__ u64 pk2(float lo, float hi) {
    u64 r; asm("mov.b64 %0, {%1, %2};" : "=l"(r) : "f"(lo), "f"(hi)); return r;
}
__device__ __forceinline__ void up2(float& lo, float& hi, u64 a) {
    asm("mov.b64 {%0, %1}, %2;" : "=f"(lo), "=f"(hi) : "l"(a));
}
__device__ __forceinline__ u64 fma2(u64 a, u64 b, u64 c) {
    u64 d; asm("fma.rn.f32x2 %0, %1, %2, %3;" : "=l"(d) : "l"(a), "l"(b), "l"(c)); return d;
}
__device__ __forceinline__ u64 mul2(u64 a, u64 b) {
    u64 d; asm("mul.rn.f32x2 %0, %1, %2;" : "=l"(d) : "l"(a), "l"(b)); return d;
}
__device__ __forceinline__ float silu_f(float v) { return v / (1.0f + __expf(-v)); }

// ---------------- precompute W_combo = (W1*S1) @ (We*S2) ----------------
__global__ void combo_kernel(const float* __restrict__ W1, const float* __restrict__ We) {
    constexpr float S1 = 1.6789f * 0.125f;
    constexpr float S2 = 0.08838834764831845f;
    int idx = blockIdx.x * blockDim.x + threadIdx.x;
    if (idx >= 64 * 160) return;
    int r = idx / 160, c = idx % 160;
    float acc = 0.0f;
#pragma unroll 8
    for (int k = 0; k < 128; k++) acc = fmaf(W1[r * 128 + k], We[k * 160 + c], acc);
    g_wcombo[idx] = acc * (S1 * S2);
}

// 32-col GEMM chunk: acc[16 u64] += h[0..63] (regs) * W[j][c0..c0+31] (smem)
template <int STRIDE>
__device__ __forceinline__ void gemm32(const float* __restrict__ w0,
                                       const float* __restrict__ h,
                                       u64* __restrict__ acc) {
#pragma unroll
    for (int j = 0; j < 64; j++) {
        const u64 h2 = pk2(h[j], h[j]);
        const ulonglong2* w = reinterpret_cast<const ulonglong2*>(w0 + j * STRIDE);
#pragma unroll
        for (int q = 0; q < 8; q++) {
            ulonglong2 wv = w[q];
            acc[2 * q]     = fma2(h2, wv.x, acc[2 * q]);
            acc[2 * q + 1] = fma2(h2, wv.y, acc[2 * q + 1]);
        }
    }
}

__global__ void __launch_bounds__(THREADS, 1)
e3_fused_kernel(const int*   __restrict__ eidx,
                const float* __restrict__ esh,
                const float* __restrict__ elen,
                const float* __restrict__ onehot,
                const float* __restrict__ bw,
                const float* __restrict__ tpw,
                const float* __restrict__ W0,
                const float* __restrict__ W1,
                float*       __restrict__ out,
                int E)
{
    extern __shared__ float sm[];
    constexpr float S1 = 1.6789f * 0.125f;   // SILU_CST/sqrt(64)

    // ---- cooperative loads: bessel rows raw, W1 prescaled, WC, consts ----
    sm[SM_BES + threadIdx.x] = W0[32 * 64 + threadIdx.x];          // 512 floats
#pragma unroll
    for (int i = threadIdx.x; i < 64 * 128; i += THREADS) sm[SM_W1 + i] = W1[i] * S1;
#pragma unroll
    for (int i = threadIdx.x; i < 64 * 160; i += THREADS) sm[SM_WC + i] = g_wcombo[i];
    if (threadIdx.x < 8)       sm[SM_CST + threadIdx.x] = bw[threadIdx.x];
    else if (threadIdx.x < 15) sm[SM_CST + threadIdx.x] = tpw[threadIdx.x - 8];
    __syncthreads();

    const int lane  = threadIdx.x & 31;
    const int warp  = threadIdx.x >> 5;
    float* buf = sm + SM_BUF   + warp * 1056;
    float* st  = sm + SM_STASH + warp * 1056;
    const int e     = blockIdx.x * THREADS + threadIdx.x;
    const int ebase = blockIdx.x * THREADS + warp * 32;

    float* __restrict__ lat_out  = out;
    float* __restrict__ feat_out = out + (size_t)E * 128;
    float* __restrict__ cut_out  = out + (size_t)E * 416;

    // ---- per-edge loads ----
    const int   src = eidx[e];
    const int   dst = eidx[E + e];
    const float r   = elen[e];
    const float4 shv = reinterpret_cast<const float4*>(esh)[e];

    int ts = 0, td = 0;
    {
        const float4* rs = reinterpret_cast<const float4*>(onehot + (size_t)src * 16);
        const float4* rd = reinterpret_cast<const float4*>(onehot + (size_t)dst * 16);
#pragma unroll
        for (int q4 = 0; q4 < 4; q4++) {
            float4 a = __ldg(rs + q4); float4 b = __ldg(rd + q4);
            int base = q4 * 4;
            if (a.x > 0.5f) ts = base;     if (a.y > 0.5f) ts = base + 1;
            if (a.z > 0.5f) ts = base + 2; if (a.w > 0.5f) ts = base + 3;
            if (b.x > 0.5f) td = base;     if (b.y > 0.5f) td = base + 1;
            if (b.z > 0.5f) td = base + 2; if (b.w > 0.5f) td = base + 3;
        }
    }

    const float x    = r * 0.2f;
    const float invr = 1.0f / r;
    float eb[8];
#pragma unroll
    for (int j = 0; j < 8; j++)
        eb[j] = 0.4f * __sinf(sm[SM_CST + j] * x) * invr;

    const float x3 = x * x * x, x6 = x3 * x3, x7 = x6 * x, x8 = x7 * x;
    const float poly = 1.0f - 28.0f * x6 + 48.0f * x7 - 21.0f * x8;
    const float cutv = (x < 1.0f) ? poly : 0.0f;
    const float cl   = (cutv > 0.0f) ? cutv : 0.0f;
    cut_out[e] = cutv;

    // ---- stage 1: h[64] (REGISTERS) = silu(S0*(W0[ts]+W0[16+td]+eb@bessel_rows)) ----
    constexpr float S0 = 0.15811388300841897f;
    float h[64];
    {
        const float4* rowts = reinterpret_cast<const float4*>(W0 + ts * 64);
        const float4* rowtd = reinterpret_cast<const float4*>(W0 + (16 + td) * 64);
#pragma unroll
        for (int q = 0; q < 16; q++) {
            float4 a = __ldg(rowts + q);
            float4 b = __ldg(rowtd + q);
            h[4 * q + 0] = a.x + b.x; h[4 * q + 1] = a.y + b.y;
            h[4 * q + 2] = a.z + b.z; h[4 * q + 3] = a.w + b.w;
        }
#pragma unroll
        for (int j = 0; j < 8; j++) {
            const float bj = eb[j];
            const float4* br = reinterpret_cast<const float4*>(sm + SM_BES + j * 64);
#pragma unroll
            for (int q = 0; q < 16; q++) {
                float4 w = br[q];
                h[4 * q + 0] = fmaf(bj, w.x, h[4 * q + 0]);
                h[4 * q + 1] = fmaf(bj, w.y, h[4 * q + 1]);
                h[4 * q + 2] = fmaf(bj, w.z, h[4 * q + 2]);
                h[4 * q + 3] = fmaf(bj, w.w, h[4 * q + 3]);
            }
        }
#pragma unroll
        for (int k = 0; k < 64; k++) h[k] = silu_f(S0 * h[k]);
    }

    // ---- tensor-product scalars (cut folded) ----
    const float s = shv.x, vx = shv.y, vy = shv.z, vz = shv.w;
    const float tw0 = sm[SM_CST +  8], tw1 = sm[SM_CST +  9], tw2 = sm[SM_CST + 10];
    const float tw3 = sm[SM_CST + 11], tw4 = sm[SM_CST + 12], tw5 = sm[SM_CST + 13];
    const float tw6 = sm[SM_CST + 14];
    constexpr float SQ3  = 1.7320508075688772f;
    constexpr float INV2 = 0.70710678118654752f;

    const float sq   = s * s;
    const float dotv = (vx * vx + vy * vy + vz * vz) * (1.0f / SQ3);
    const float tp0a = (tw0 * sq + tw1 * dotv) * cl;
    const float tp0b = (tw4 * sq + tw5 * dotv) * cl;
    const float scl  = s * cl;
    float tp1a[3], tp1b[3];
    tp1a[0] = tw2 * scl * vx; tp1a[1] = tw2 * scl * vy; tp1a[2] = tw2 * scl * vz;
    tp1b[0] = tw3 * scl * vx; tp1b[1] = tw3 * scl * vy; tp1b[2] = tw3 * scl * vz;
    const float t6c = tw6 * cl;
    float tp2[5];
    tp2[0] = t6c * SQ3 * vx * vy;
    tp2[1] = t6c * SQ3 * vy * vz;
    tp2[2] = t6c * (vz * vz - 0.5f * (vx * vx + vy * vy));
    tp2[3] = t6c * SQ3 * vx * vz;
    tp2[4] = t6c * (0.5f * SQ3) * (vx * vx - vy * vy);

    u64 acc[16];
    const u64 cl2 = pk2(cl, cl);

    // ---- latents: 4 chunks of 32 cols of W1 ----
    for (int c = 0; c < 4; c++) {
#pragma unroll
        for (int q = 0; q < 16; q++) acc[q] = 0ull;
        gemm32<128>(sm + SM_W1 + c * 32, h, acc);
#pragma unroll
        for (int q = 0; q < 16; q++) {
            float a, b; up2(a, b, mul2(cl2, acc[q]));
            buf[lane * 33 + 2 * q]     = a;
            buf[lane * 33 + 2 * q + 1] = b;
        }
        __syncwarp();
#pragma unroll
        for (int rr = 0; rr < 32; rr++)
            lat_out[(size_t)(ebase + rr) * 128 + c * 32 + lane] = buf[rr * 33 + lane];
        __syncwarp();
    }

    // ---- f0: WC cols 0..31 (w0a) then 32..63 (w0b), accumulate in buf ----
    {
#pragma unroll
        for (int q = 0; q < 16; q++) acc[q] = 0ull;
        gemm32<160>(sm + SM_WC, h, acc);
#pragma unroll
        for (int q = 0; q < 16; q++) {
            float a, b; up2(a, b, acc[q]);
            buf[lane * 33 + 2 * q]     = a * tp0a;
            buf[lane * 33 + 2 * q + 1] = b * tp0b * 0.0f + b * tp0a * 0.0f + a * 0.0f + b * 0.0f + buf[lane * 33 + 2 * q + 1] * 0.0f + b * tp0a; // placeholder removed below
        }
        // NOTE: the line above is wrong style; rewrite cleanly:
#pragma unroll
        for (int q = 0; q < 16; q++) {
            float a, b; up2(a, b, acc[q]);
            buf[lane * 33 + 2 * q]     = a * tp0a;
            buf[lane * 33 + 2 * q + 1] = b * tp0a;
        }
#pragma unroll
        for (int q = 0; q < 16; q++) acc[q] = 0ull;
        gemm32<160>(sm + SM_WC + 32, h, acc);
#pragma unroll
        for (int q = 0; q < 16; q++) {
            float a, b; up2(a, b, acc[q]);
            buf[lane * 33 + 2 * q]     = INV2 * (buf[lane * 33 + 2 * q]     + a * tp0b);
            buf[lane * 33 + 2 * q + 1] = INV2 * (buf[lane * 33 + 2 * q + 1] + b * tp0b);
        }
        __syncwarp();
#pragma unroll
        for (int rr = 0; rr < 32; rr++)
            feat_out[(size_t)(ebase + rr) * 288 + lane] = buf[rr * 33 + lane];
        __syncwarp();
    }

    // ---- f1: w1a (cols 64..95) -> stash ; w1b (96..127) -> regs ; 3 output passes ----
    {
#pragma unroll
        for (int q = 0; q < 16; q++) acc[q] = 0ull;
        gemm32<160>(sm + SM_WC + 64, h, acc);
#pragma unroll
        for (int q = 0; q < 16; q++) {
            float a, b; up2(a, b, acc[q]);
            st[lane * 33 + 2 * q]     = a;
            st[lane * 33 + 2 * q + 1] = b;
        }
#pragma unroll
        for (int q = 0; q < 16; q++) acc[q] = 0ull;
        gemm32<160>(sm + SM_WC + 96, h, acc);
        float bf[32];
#pragma unroll
        for (int q = 0; q < 16; q++) up2(bf[2 * q], bf[2 * q + 1], acc[q]);
#pragma unroll
        for (int t = 0; t < 3; t++) {
#pragma unroll
            for (int u = 0; u < 32; u++) {
                const int cc = 32 * t + u, m = cc / 3, i = cc % 3;
                buf[lane * 33 + u] = INV2 * (st[lane * 33 + m] * tp1a[i] + bf[m] * tp1b[i]);
            }
            __syncwarp();
#pragma unroll
            for (int rr = 0; rr < 32; rr++)
                feat_out[(size_t)(ebase + rr) * 288 + 32 + 32 * t + lane] = buf[rr * 33 + lane];
            __syncwarp();
        }
    }

    // ---- f2: w2 (cols 128..159) -> regs ; 5 output passes ----
    {
#pragma unroll
        for (int q = 0; q < 16; q++) acc[q] = 0ull;
        gemm32<160>(sm + SM_WC + 128, h, acc);
        float cf[32];
#pragma unroll
        for (int q = 0; q < 16; q++) up2(cf[2 * q], cf[2 * q + 1], acc[q]);
#pragma unroll
        for (int t = 0; t < 5; t++) {
#pragma unroll
            for (int u = 0; u < 32; u++) {
                const int cc = 32 * t + u, m = cc / 5, i = cc % 5;
                buf[lane * 33 + u] = cf[m] * tp2[i];
            }
            __syncwarp();
#pragma unroll
            for (int rr = 0; rr < 32; rr++)
                feat_out[(size_t)(ebase + rr) * 288 + 128 + 32 * t + lane] = buf[rr * 33 + lane];
            __syncwarp();
        }
    }
}

extern "C" void kernel_launch(void* const* d_in, const int* in_sizes, int n_in,
                              void* d_out, int out_size)
{
    const int*   eidx   = (const int*)  d_in[0];
    const float* esh    = (const float*)d_in[1];
    const float* elen   = (const float*)d_in[2];
    const float* onehot = (const float*)d_in[3];
    const float* bw     = (const float*)d_in[4];
    const float* tpw    = (const float*)d_in[5];
    const float* W0     = (const float*)d_in[6];
    const float* W1     = (const float*)d_in[7];
    const float* We     = (const float*)d_in[8];
    float* out = (float*)d_out;

    const int E = in_sizes[0] / 2;       // 524288
    const int blocks = E / THREADS;      // 1024

    combo_kernel<<<(64 * 160 + 255) / 256, 256>>>(W1, We);

    cudaFuncSetAttribute(e3_fused_kernel,
                         cudaFuncAttributeMaxDynamicSharedMemorySize, SMEM_BYTES);
    e3_fused_kernel<<<blocks, THREADS, SMEM_BYTES>>>(
        eidx, esh, elen, onehot, bw, tpw, W0, W1, out, E);
}

// round 6
// speedup vs baseline: 1.2032x; 1.2032x over previous
#include <cuda_runtime.h>
#include <cstdint>

typedef unsigned long long u64;

// ---------------- constants ----------------
constexpr int THREADS = 512;
constexpr int EPB     = 1024;            // edges per block (2 per thread)

// smem layout (floats) — identical budget to R3 (152 KB)
constexpr int SM_W0   = 0;                  // 40 rows x stride 68
constexpr int SM_W1   = 40 * 68;            // 2720 : 64 x 128 (prescaled S1)
constexpr int SM_WC   = SM_W1 + 64 * 128;   // 10912 : 64 x 160 (W1s @ We s)
constexpr int SM_CST  = SM_WC + 64 * 160;   // 21152 : bessel_w[8], tpw[7]
constexpr int SM_BUF  = SM_CST + 16;        // 21168 : 16 warps * 1056
constexpr int SMEM_FLOATS = SM_BUF + 16 * 1056;
constexpr int SMEM_BYTES  = SMEM_FLOATS * 4;  // 152,256 B

// ---------------- device scratch ----------------
__device__ float g_wcombo[64 * 160];

// ---------------- f32x2 helpers ----------------
__device__ __forceinline__ u64 pk2(float lo, float hi) {
    u64 r; asm("mov.b64 %0, {%1, %2};" : "=l"(r) : "f"(lo), "f"(hi)); return r;
}
__device__ __forceinline__ void up2(float& lo, float& hi, u64 a) {
    asm("mov.b64 {%0, %1}, %2;" : "=f"(lo), "=f"(hi) : "l"(a));
}
__device__ __forceinline__ u64 fma2(u64 a, u64 b, u64 c) {
    u64 d; asm("fma.rn.f32x2 %0, %1, %2, %3;" : "=l"(d) : "l"(a), "l"(b), "l"(c)); return d;
}
__device__ __forceinline__ u64 add2(u64 a, u64 b) {
    u64 d; asm("add.rn.f32x2 %0, %1, %2;" : "=l"(d) : "l"(a), "l"(b)); return d;
}
__device__ __forceinline__ u64 mul2(u64 a, u64 b) {
    u64 d; asm("mul.rn.f32x2 %0, %1, %2;" : "=l"(d) : "l"(a), "l"(b)); return d;
}
__device__ __forceinline__ float silu_f(float v) { return v / (1.0f + __expf(-v)); }

// ---------------- precompute W_combo = (W1*S1) @ (We*S2) ----------------
__global__ void combo_kernel(const float* __restrict__ W1, const float* __restrict__ We) {
    constexpr float S1 = 1.6789f * 0.125f;
    constexpr float S2 = 0.08838834764831845f;
    int idx = blockIdx.x * blockDim.x + threadIdx.x;
    if (idx >= 64 * 160) return;
    int r = idx / 160, c = idx % 160;
    float acc = 0.0f;
#pragma unroll 8
    for (int k = 0; k < 128; k++) acc = fmaf(W1[r * 128 + k], We[k * 160 + c], acc);
    g_wcombo[idx] = acc * (S1 * S2);
}

// ---- 64-col single-edge chunk: acc[32 u64] += h[j] * W[j][0..63] ----
__device__ __forceinline__ void gemm64(const float* __restrict__ w0, int stride,
                                       const float* __restrict__ h2, u64* __restrict__ acc) {
#pragma unroll 4
    for (int j = 0; j < 64; j++) {
        const float hj = h2[2 * j];
        const u64 hh = pk2(hj, hj);
        const ulonglong2* wr = reinterpret_cast<const ulonglong2*>(w0 + j * stride);
#pragma unroll
        for (int q = 0; q < 16; q++) {
            ulonglong2 w = wr[q];
            acc[2 * q]     = fma2(hh, w.x, acc[2 * q]);
            acc[2 * q + 1] = fma2(hh, w.y, acc[2 * q + 1]);
        }
    }
}

// ---- 32-col two-edge chunk: one weight LDS feeds both edges ----
__device__ __forceinline__ void gemm32p(const float* __restrict__ w0, int stride,
                                        const float2* __restrict__ h2,
                                        u64* __restrict__ aA, u64* __restrict__ aB) {
#pragma unroll 4
    for (int j = 0; j < 64; j++) {
        const float2 hj = h2[j];
        const u64 ha = pk2(hj.x, hj.x);
        const u64 hb = pk2(hj.y, hj.y);
        const ulonglong2* wr = reinterpret_cast<const ulonglong2*>(w0 + j * stride);
#pragma unroll
        for (int q = 0; q < 8; q++) {
            ulonglong2 w = wr[q];
            aA[2 * q]     = fma2(ha, w.x, aA[2 * q]);
            aA[2 * q + 1] = fma2(ha, w.y, aA[2 * q + 1]);
            aB[2 * q]     = fma2(hb, w.x, aB[2 * q]);
            aB[2 * q + 1] = fma2(hb, w.y, aB[2 * q + 1]);
        }
    }
}

__global__ void __launch_bounds__(THREADS, 1)
e3_fused_kernel(const int*   __restrict__ eidx,
                const float* __restrict__ esh,
                const float* __restrict__ elen,
                const float* __restrict__ onehot,
                const float* __restrict__ bw,
                const float* __restrict__ tpw,
                const float* __restrict__ W0,
                const float* __restrict__ W1,
                float*       __restrict__ out,
                int E)
{
    extern __shared__ float sm[];
    constexpr float S0 = 0.15811388300841897f;   // 1/sqrt(40)
    constexpr float S1 = 1.6789f * 0.125f;       // SILU_CST/sqrt(64)

    // ---- cooperative weight load (pre-scaled) ----
    for (int i = threadIdx.x; i < 40 * 64; i += THREADS) {
        int r = i >> 6, k = i & 63;
        sm[SM_W0 + r * 68 + k] = W0[i] * S0;
    }
    for (int i = threadIdx.x; i < 64 * 128; i += THREADS) sm[SM_W1 + i] = W1[i] * S1;
    for (int i = threadIdx.x; i < 64 * 160; i += THREADS) sm[SM_WC + i] = g_wcombo[i];
    if (threadIdx.x < 8)       sm[SM_CST + threadIdx.x] = bw[threadIdx.x];
    else if (threadIdx.x < 15) sm[SM_CST + threadIdx.x] = tpw[threadIdx.x - 8];
    __syncthreads();

    const int lane  = threadIdx.x & 31;
    const int warp  = threadIdx.x >> 5;
    float* buf = sm + SM_BUF + warp * 1056;

    const int e0     = blockIdx.x * EPB + threadIdx.x;
    const int e1     = e0 + THREADS;
    const int ebase0 = blockIdx.x * EPB + warp * 32;
    const int ebase1 = ebase0 + THREADS;

    float* __restrict__ lat_out  = out;
    float* __restrict__ feat_out = out + (size_t)E * 128;
    float* __restrict__ cut_out  = out + (size_t)E * 416;

    // ================= stage 0/1 for both edges =================
    float2 hloc2[64];              // interleaved h for edges A/B (local mem)
    float4 shvE[2];
    float  clE[2];

#pragma unroll
    for (int ei = 0; ei < 2; ei++) {
        const int e = ei ? e1 : e0;
        const int   src = eidx[e];
        const int   dst = eidx[E + e];
        const float r   = elen[e];
        shvE[ei] = reinterpret_cast<const float4*>(esh)[e];

        int ts = 0, td = 0;
        {
            const float4* rs = reinterpret_cast<const float4*>(onehot + (size_t)src * 16);
            const float4* rd = reinterpret_cast<const float4*>(onehot + (size_t)dst * 16);
#pragma unroll
            for (int q4 = 0; q4 < 4; q4++) {
                float4 a = __ldg(rs + q4); float4 b = __ldg(rd + q4);
                int base = q4 * 4;
                if (a.x > 0.5f) ts = base;     if (a.y > 0.5f) ts = base + 1;
                if (a.z > 0.5f) ts = base + 2; if (a.w > 0.5f) ts = base + 3;
                if (b.x > 0.5f) td = base;     if (b.y > 0.5f) td = base + 1;
                if (b.z > 0.5f) td = base + 2; if (b.w > 0.5f) td = base + 3;
            }
        }

        const float x    = r * 0.2f;
        const float invr = 1.0f / r;
        float eb[8];
#pragma unroll
        for (int j = 0; j < 8; j++)
            eb[j] = 0.4f * __sinf(sm[SM_CST + j] * x) * invr;

        const float x3 = x * x * x, x6 = x3 * x3, x7 = x6 * x, x8 = x7 * x;
        const float poly = 1.0f - 28.0f * x6 + 48.0f * x7 - 21.0f * x8;
        const float cutv = (x < 1.0f) ? poly : 0.0f;
        clE[ei] = (cutv > 0.0f) ? cutv : 0.0f;
        cut_out[e] = cutv;

        // h = silu( W0s[ts] + W0s[16+td] + eb @ W0s[32..39] )   (W0s prescaled S0)
        float hacc[64];
        const float* w0s = sm + SM_W0 + ts * 68;
        const float* w0d = sm + SM_W0 + (16 + td) * 68;
#pragma unroll
        for (int k = 0; k < 64; k++) hacc[k] = w0s[k] + w0d[k];
#pragma unroll
        for (int j = 0; j < 8; j++) {
            const float bj = eb[j];
            const float* wr = sm + SM_W0 + (32 + j) * 68;
#pragma unroll
            for (int k = 0; k < 64; k++) hacc[k] = fmaf(bj, wr[k], hacc[k]);
        }
        float* hout = reinterpret_cast<float*>(hloc2) + ei;
#pragma unroll
        for (int k = 0; k < 64; k++) hout[2 * k] = silu_f(hacc[k]);
    }

    constexpr float SQ3  = 1.7320508075688772f;
    constexpr float INV2 = 0.70710678118654752f;
    const float tw0 = sm[SM_CST +  8], tw1 = sm[SM_CST +  9], tw2 = sm[SM_CST + 10];
    const float tw3 = sm[SM_CST + 11], tw4 = sm[SM_CST + 12], tw5 = sm[SM_CST + 13];
    const float tw6 = sm[SM_CST + 14];

    // ================= latents: 4 paired 32-col chunks of W1 =================
    for (int c = 0; c < 4; c++) {
        u64 aA[16], aB[16];
#pragma unroll
        for (int q = 0; q < 16; q++) { aA[q] = 0ull; aB[q] = 0ull; }
        gemm32p(sm + SM_W1 + c * 32, 128, hloc2, aA, aB);
#pragma unroll
        for (int ei = 0; ei < 2; ei++) {
            const u64* ac = ei ? aB : aA;
            const u64 cl2 = pk2(clE[ei], clE[ei]);
            const int eb_ = ei ? ebase1 : ebase0;
#pragma unroll
            for (int q = 0; q < 16; q++) {
                float a, b; up2(a, b, mul2(cl2, ac[q]));
                buf[lane * 33 + 2 * q]     = a;
                buf[lane * 33 + 2 * q + 1] = b;
            }
            __syncwarp();
#pragma unroll
            for (int rr = 0; rr < 32; rr++)
                lat_out[(size_t)(eb_ + rr) * 128 + c * 32 + lane] = buf[rr * 33 + lane];
            __syncwarp();
        }
    }

    // ================= f2: paired 32-col chunk (WC cols 128..159) =================
    {
        u64 aA[16], aB[16];
#pragma unroll
        for (int q = 0; q < 16; q++) { aA[q] = 0ull; aB[q] = 0ull; }
        gemm32p(sm + SM_WC + 128, 160, hloc2, aA, aB);
#pragma unroll
        for (int ei = 0; ei < 2; ei++) {
            const u64* ac = ei ? aB : aA;
            const int eb_ = ei ? ebase1 : ebase0;
            const float4 sv = shvE[ei];
            const float vx = sv.y, vy = sv.z, vz = sv.w;
            const float t6c = tw6 * clE[ei];
            float tp2[5];
            tp2[0] = t6c * SQ3 * vx * vy;
            tp2[1] = t6c * SQ3 * vy * vz;
            tp2[2] = t6c * (vz * vz - 0.5f * (vx * vx + vy * vy));
            tp2[3] = t6c * SQ3 * vx * vz;
            tp2[4] = t6c * (0.5f * SQ3) * (vx * vx - vy * vy);
            float cf[32];
#pragma unroll
            for (int q = 0; q < 16; q++) up2(cf[2 * q], cf[2 * q + 1], ac[q]);
#pragma unroll
            for (int t = 0; t < 5; t++) {
#pragma unroll
                for (int u = 0; u < 32; u++) {
                    const int cc = 32 * t + u, m = cc / 5, i = cc % 5;
                    buf[lane * 33 + u] = cf[m] * tp2[i];
                }
                __syncwarp();
#pragma unroll
                for (int rr = 0; rr < 32; rr++)
                    feat_out[(size_t)(eb_ + rr) * 288 + 128 + 32 * t + lane] = buf[rr * 33 + lane];
                __syncwarp();
            }
        }
    }

    // ================= f0 + f1: per-edge 64-col chunks =================
#pragma unroll
    for (int ei = 0; ei < 2; ei++) {
        const float* hptr = reinterpret_cast<const float*>(hloc2) + ei;
        const int eb_ = ei ? ebase1 : ebase0;
        const float4 sv = shvE[ei];
        const float cl = clE[ei];
        const float s = sv.x, vx = sv.y, vy = sv.z, vz = sv.w;
        const float sq   = s * s;
        const float dotv = (vx * vx + vy * vy + vz * vz) * (1.0f / SQ3);
        const float tp0a = (tw0 * sq + tw1 * dotv) * cl;
        const float tp0b = (tw4 * sq + tw5 * dotv) * cl;
        const float scl  = s * cl;
        float tp1a[3], tp1b[3];
        tp1a[0] = tw2 * scl * vx; tp1a[1] = tw2 * scl * vy; tp1a[2] = tw2 * scl * vz;
        tp1b[0] = tw3 * scl * vx; tp1b[1] = tw3 * scl * vy; tp1b[2] = tw3 * scl * vz;

        // ---- f0: WC cols 0..63 ----
        {
            u64 acc[32];
#pragma unroll
            for (int q = 0; q < 32; q++) acc[q] = 0ull;
            gemm64(sm + SM_WC, 160, hptr, acc);
            float accf[64];
#pragma unroll
            for (int q = 0; q < 32; q++) up2(accf[2 * q], accf[2 * q + 1], acc[q]);
#pragma unroll
            for (int u = 0; u < 32; u++)
                buf[lane * 33 + u] = INV2 * (accf[u] * tp0a + accf[32 + u] * tp0b);
            __syncwarp();
#pragma unroll
            for (int rr = 0; rr < 32; rr++)
                feat_out[(size_t)(eb_ + rr) * 288 + lane] = buf[rr * 33 + lane];
            __syncwarp();
        }

        // ---- f1: WC cols 64..127 ----
        {
            u64 acc[32];
#pragma unroll
            for (int q = 0; q < 32; q++) acc[q] = 0ull;
            gemm64(sm + SM_WC + 64, 160, hptr, acc);
            float accf[64];
#pragma unroll
            for (int q = 0; q < 32; q++) up2(accf[2 * q], accf[2 * q + 1], acc[q]);
#pragma unroll
            for (int t = 0; t < 3; t++) {
#pragma unroll
                for (int u = 0; u < 32; u++) {
                    const int cc = 32 * t + u, m = cc / 3, i = cc % 3;
                    buf[lane * 33 + u] = INV2 * (accf[m] * tp1a[i] + accf[32 + m] * tp1b[i]);
                }
                __syncwarp();
#pragma unroll
                for (int rr = 0; rr < 32; rr++)
                    feat_out[(size_t)(eb_ + rr) * 288 + 32 + 32 * t + lane] = buf[rr * 33 + lane];
                __syncwarp();
            }
        }
    }
}

extern "C" void kernel_launch(void* const* d_in, const int* in_sizes, int n_in,
                              void* d_out, int out_size)
{
    const int*   eidx   = (const int*)  d_in[0];
    const float* esh    = (const float*)d_in[1];
    const float* elen   = (const float*)d_in[2];
    const float* onehot = (const float*)d_in[3];
    const float* bw     = (const float*)d_in[4];
    const float* tpw    = (const float*)d_in[5];
    const float* W0     = (const float*)d_in[6];
    const float* W1     = (const float*)d_in[7];
    const float* We     = (const float*)d_in[8];
    float* out = (float*)d_out;

    const int E = in_sizes[0] / 2;       // 524288
    const int blocks = E / EPB;          // 512

    combo_kernel<<<(64 * 160 + 255) / 256, 256>>>(W1, We);

    cudaFuncSetAttribute(e3_fused_kernel,
                         cudaFuncAttributeMaxDynamicSharedMemorySize, SMEM_BYTES);
    e3_fused_kernel<<<blocks, THREADS, SMEM_BYTES>>>(
        eidx, esh, elen, onehot, bw, tpw, W0, W1, out, E);
}